// round 6
// baseline (speedup 1.0000x reference)
#include <cuda_runtime.h>
#include <cuda_bf16.h>
#include <cstdint>

#define NN 50000
#define NE 800000
#define FD 128
#define NBITS 64
#define NCLS 100
#define HDIM 300

// ---------------- scratch (device globals: allocation-free) ----------------
__device__ int   g_cursor[NN];
__device__ int   g_rowptr[NN + 1];
__device__ int   g_col[NE];
__device__ float g_h1f[NN * FD];            // fp32 h1 (for layer-2 aggregation)
__device__ float g_prebn[NN * NBITS];

// bf16 hi/lo operand planes
__device__ __nv_bfloat16 g_fh[NN * FD],  g_fl[NN * FD];    // features
__device__ __nv_bfloat16 g_mh[NN * FD],  g_ml[NN * FD];    // mean (reused both layers)
__device__ __nv_bfloat16 g_h1h[NN * FD], g_h1l[NN * FD];   // h1
__device__ __nv_bfloat16 g_h2h[NN * FD], g_h2l[NN * FD];   // h2
__device__ __nv_bfloat16 g_oh[NN * NBITS], g_ol[NN * NBITS]; // tanh out
// transposed weight planes [N x K], concatenated
#define WT_W1L 0
#define WT_W1R 16384
#define WT_W2L 32768
#define WT_W2R 49152
#define WT_WHD 65536
#define WT_WCLAS 103936
#define WT_WCONV 116736
#define WT_WCV 124928
#define WT_TOTAL 131328
__device__ __nv_bfloat16 g_wth[WT_TOTAL], g_wtl[WT_TOTAL];

// ---------------- helpers ----------------
__device__ __forceinline__ uint32_t smem_u32(const void* p) {
    uint32_t a;
    asm("{ .reg .u64 t; cvta.to.shared.u64 t, %1; cvt.u32.u64 %0, t; }" : "=r"(a) : "l"(p));
    return a;
}
__device__ __forceinline__ void cpa16(uint32_t dst, const void* src, int sz) {
    asm volatile("cp.async.ca.shared.global [%0], [%1], 16, %2;"
                 :: "r"(dst), "l"(src), "r"(sz));
}
__device__ __forceinline__ void cpa_wait() {
    asm volatile("cp.async.commit_group;\n\tcp.async.wait_group 0;" ::: "memory");
}
__device__ __forceinline__ void ldsm4(uint32_t& r0, uint32_t& r1, uint32_t& r2, uint32_t& r3,
                                      uint32_t addr) {
    asm volatile("ldmatrix.sync.aligned.m8n8.x4.shared.b16 {%0,%1,%2,%3}, [%4];"
                 : "=r"(r0), "=r"(r1), "=r"(r2), "=r"(r3) : "r"(addr));
}
__device__ __forceinline__ void mma16816(float* c, uint32_t a0, uint32_t a1, uint32_t a2,
                                         uint32_t a3, uint32_t b0, uint32_t b1) {
    asm volatile("mma.sync.aligned.m16n8k16.row.col.f32.bf16.bf16.f32 "
                 "{%0,%1,%2,%3},{%4,%5,%6,%7},{%8,%9},{%0,%1,%2,%3};"
                 : "+f"(c[0]), "+f"(c[1]), "+f"(c[2]), "+f"(c[3])
                 : "r"(a0), "r"(a1), "r"(a2), "r"(a3), "r"(b0), "r"(b1));
}
template <int RB>
__device__ __forceinline__ int swoff(int row, int k) {
    return row * RB + (((k >> 3) ^ (row & 7)) << 4) + ((k & 7) << 1);
}
__device__ __forceinline__ uint32_t pack_hi(float x, float y) {
    __nv_bfloat162 t = __floats2bfloat162_rn(x, y);
    return *(uint32_t*)&t;
}
__device__ __forceinline__ uint32_t pack_lo(float x, float y) {
    float hx = __bfloat162float(__float2bfloat16(x));
    float hy = __bfloat162float(__float2bfloat16(y));
    __nv_bfloat162 t = __floats2bfloat162_rn(x - hx, y - hy);
    return *(uint32_t*)&t;
}

// ---------------- plane producers ----------------
// fp32 [n4*4] -> hi/lo planes, 4 elems per thread
__global__ void conv_k(const float* __restrict__ x, __nv_bfloat16* __restrict__ h,
                       __nv_bfloat16* __restrict__ l, int n4) {
    int i = blockIdx.x * blockDim.x + threadIdx.x;
    if (i >= n4) return;
    float4 v = ((const float4*)x)[i];
    uint2 hv = make_uint2(pack_hi(v.x, v.y), pack_hi(v.z, v.w));
    uint2 lv = make_uint2(pack_lo(v.x, v.y), pack_lo(v.z, v.w));
    ((uint2*)h)[i] = hv;
    ((uint2*)l)[i] = lv;
}

// W [Kd x Nd] fp32 -> transposed planes [Nd x Kd] bf16 hi/lo
__global__ void wpackT_k(const float* __restrict__ s, __nv_bfloat16* __restrict__ dh,
                         __nv_bfloat16* __restrict__ dl, int Kd, int Nd) {
    int idx = blockIdx.x * blockDim.x + threadIdx.x;
    int c8 = Kd >> 3;
    if (idx >= Nd * c8) return;
    int n = idx / c8, k0 = (idx % c8) * 8;
    uint32_t h[4], l[4];
    #pragma unroll
    for (int q = 0; q < 4; q++) {
        float v0 = s[(size_t)(k0 + 2 * q) * Nd + n];
        float v1 = s[(size_t)(k0 + 2 * q + 1) * Nd + n];
        h[q] = pack_hi(v0, v1);
        l[q] = pack_lo(v0, v1);
    }
    *(uint4*)(dh + (size_t)n * Kd + k0) = *(uint4*)h;
    *(uint4*)(dl + (size_t)n * Kd + k0) = *(uint4*)l;
}

// ---------------- CSR build ----------------
__global__ void zero_k() {
    int i = blockIdx.x * blockDim.x + threadIdx.x;
    if (i < NN) g_cursor[i] = 0;
}
__global__ void hist_k(const int* __restrict__ dst) {
    for (int e = blockIdx.x * blockDim.x + threadIdx.x; e < NE; e += gridDim.x * blockDim.x)
        atomicAdd(&g_cursor[dst[e]], 1);
}
// single-block full exclusive scan of g_cursor[NN] -> g_rowptr, cursor
__global__ void scan_all_k() {
    const int T = 1024;
    const int PER = (NN + T - 1) / T;   // 49
    int tid = threadIdx.x;
    int base = tid * PER;
    int lim = NN - base; if (lim < 0) lim = 0; if (lim > PER) lim = PER;
    int sum = 0;
    for (int j = 0; j < lim; j++) sum += g_cursor[base + j];
    int lane = tid & 31, w = tid >> 5;
    int x = sum;
    #pragma unroll
    for (int o = 1; o < 32; o <<= 1) {
        int y = __shfl_up_sync(0xffffffffu, x, o);
        if (lane >= o) x += y;
    }
    __shared__ int ws[32];
    if (lane == 31) ws[w] = x;
    __syncthreads();
    if (w == 0) {
        int s = ws[lane];
        #pragma unroll
        for (int o = 1; o < 32; o <<= 1) {
            int y = __shfl_up_sync(0xffffffffu, s, o);
            if (lane >= o) s += y;
        }
        ws[lane] = s;
    }
    __syncthreads();
    int run = x - sum + (w > 0 ? ws[w - 1] : 0);
    for (int j = 0; j < lim; j++) {
        int i = base + j;
        int cnt = g_cursor[i];
        g_rowptr[i] = run;
        g_cursor[i] = run;
        run += cnt;
    }
    if (tid == 0) g_rowptr[NN] = NE;
}
__global__ void scatter_k(const int* __restrict__ src, const int* __restrict__ dst) {
    for (int e = blockIdx.x * blockDim.x + threadIdx.x; e < NE; e += gridDim.x * blockDim.x) {
        int pos = atomicAdd(&g_cursor[dst[e]], 1);
        g_col[pos] = src[e];
    }
}

// ---------------- mean aggregation: one warp per node, writes hi/lo planes --------
__global__ void agg_k(const float* __restrict__ x, __nv_bfloat16* __restrict__ mh,
                      __nv_bfloat16* __restrict__ ml) {
    int warp = blockIdx.x * (blockDim.x >> 5) + (threadIdx.x >> 5);
    int lane = threadIdx.x & 31;
    if (warp >= NN) return;
    int beg = g_rowptr[warp], end = g_rowptr[warp + 1];
    float4 acc = make_float4(0.f, 0.f, 0.f, 0.f);
    for (int e = beg; e < end; ++e) {
        int s = __ldg(&g_col[e]);
        float4 v = *(const float4*)(x + (size_t)s * FD + lane * 4);
        acc.x += v.x; acc.y += v.y; acc.z += v.z; acc.w += v.w;
    }
    float sc = 1.f / (float)max(end - beg, 1);
    float r0 = acc.x * sc, r1 = acc.y * sc, r2 = acc.z * sc, r3 = acc.w * sc;
    size_t o = (size_t)warp * FD + lane * 4;
    *(uint2*)(mh + o) = make_uint2(pack_hi(r0, r1), pack_hi(r2, r3));
    *(uint2*)(ml + o) = make_uint2(pack_lo(r0, r1), pack_lo(r2, r3));
}

// ---------------- mma.sync bf16-split GEMM (plane operands, cp.async staging) ------
// MODE 0: out fp32 only
// MODE 1: relu -> out fp32 + outh/outl planes
// MODE 2: BN+tanh -> out fp32 (tanh) + planes of tanh + prebn fp32
template <int MODE, bool DUAL, int K>
__global__ void __launch_bounds__(256)
mm_kernel(const __nv_bfloat16* __restrict__ A1h, const __nv_bfloat16* __restrict__ A1l,
          const __nv_bfloat16* __restrict__ A2h, const __nv_bfloat16* __restrict__ A2l,
          const __nv_bfloat16* __restrict__ W1h, const __nv_bfloat16* __restrict__ W1l,
          const __nv_bfloat16* __restrict__ W2h, const __nv_bfloat16* __restrict__ W2l,
          const float* __restrict__ bias, float* __restrict__ out,
          __nv_bfloat16* __restrict__ outh, __nv_bfloat16* __restrict__ outl,
          int M, int N,
          const float* __restrict__ gamma, const float* __restrict__ beta,
          const float* __restrict__ rmean, const float* __restrict__ rvar,
          float* __restrict__ preout)
{
    constexpr int RB  = K * 2;
    constexpr int ATB = 128 * RB;
    constexpr int BTB = 64 * RB;
    constexpr int CH  = K / 8;          // 16B chunks per row
    extern __shared__ __align__(16) char smem[];
    uint32_t sbase = smem_u32(smem);
    uint32_t sAhi = sbase, sAlo = sbase + ATB, sBhi = sbase + 2 * ATB, sBlo = sbase + 2 * ATB + BTB;

    int tid = threadIdx.x, lane = tid & 31, wid = tid >> 5;
    int wm  = (wid & 3) * 32;
    int wnw = (wid >> 2) * 32;
    int gm  = blockIdx.x * 128;
    int wn  = blockIdx.y * 64;

    float c[2][4][4];
    #pragma unroll
    for (int i = 0; i < 2; i++)
        #pragma unroll
        for (int j = 0; j < 4; j++)
            #pragma unroll
            for (int q = 0; q < 4; q++) c[i][j][q] = 0.f;

    int a_row = (lane & 15);
    int a_kof = (lane >> 1) & 8;
    int b_row = (lane & 7) + ((lane >> 1) & 8);
    int b_kof = lane & 8;

    const int npair = DUAL ? 2 : 1;
    for (int pair = 0; pair < npair; ++pair) {
        const __nv_bfloat16* Ah = pair ? A2h : A1h;
        const __nv_bfloat16* Al = pair ? A2l : A1l;
        const __nv_bfloat16* Wh = pair ? W2h : W1h;
        const __nv_bfloat16* Wl = pair ? W2l : W1l;

        // A planes: 128 rows x CH chunks
        #pragma unroll 2
        for (int cc = tid; cc < 128 * CH; cc += 256) {
            int row = cc / CH, ch = cc - row * CH;
            int grow = gm + row;
            int sz = (grow < M) ? 16 : 0;
            uint32_t doff = (uint32_t)(row * RB + ((ch ^ (row & 7)) << 4));
            size_t so = (size_t)grow * K + ch * 8;
            cpa16(sAhi + doff, Ah + so, sz);
            cpa16(sAlo + doff, Al + so, sz);
        }
        // B planes: 64 rows x CH chunks
        #pragma unroll 2
        for (int cc = tid; cc < 64 * CH; cc += 256) {
            int n = cc / CH, ch = cc - n * CH;
            int gn = wn + n;
            int sz = (gn < N) ? 16 : 0;
            uint32_t doff = (uint32_t)(n * RB + ((ch ^ (n & 7)) << 4));
            size_t so = (size_t)gn * K + ch * 8;
            cpa16(sBhi + doff, Wh + so, sz);
            cpa16(sBlo + doff, Wl + so, sz);
        }
        cpa_wait();
        __syncthreads();

        #pragma unroll
        for (int k0 = 0; k0 < K; k0 += 16) {
            uint32_t ah[2][4], al[2][4], bh[4][2], bl[4][2];
            #pragma unroll
            for (int mt = 0; mt < 2; mt++) {
                int oh = swoff<RB>(wm + mt * 16 + a_row, k0 + a_kof);
                ldsm4(ah[mt][0], ah[mt][1], ah[mt][2], ah[mt][3], sAhi + oh);
                ldsm4(al[mt][0], al[mt][1], al[mt][2], al[mt][3], sAlo + oh);
            }
            #pragma unroll
            for (int g = 0; g < 2; g++) {
                int ob = swoff<RB>(wnw + g * 16 + b_row, k0 + b_kof);
                ldsm4(bh[g * 2][0], bh[g * 2][1], bh[g * 2 + 1][0], bh[g * 2 + 1][1], sBhi + ob);
                ldsm4(bl[g * 2][0], bl[g * 2][1], bl[g * 2 + 1][0], bl[g * 2 + 1][1], sBlo + ob);
            }
            #pragma unroll
            for (int mt = 0; mt < 2; mt++)
                #pragma unroll
                for (int nt = 0; nt < 4; nt++) {
                    mma16816(c[mt][nt], ah[mt][0], ah[mt][1], ah[mt][2], ah[mt][3],
                             bh[nt][0], bh[nt][1]);
                    mma16816(c[mt][nt], ah[mt][0], ah[mt][1], ah[mt][2], ah[mt][3],
                             bl[nt][0], bl[nt][1]);
                    mma16816(c[mt][nt], al[mt][0], al[mt][1], al[mt][2], al[mt][3],
                             bh[nt][0], bh[nt][1]);
                }
        }
        __syncthreads();
    }

    // epilogue
    int g  = lane >> 2;
    int tc = (lane & 3) * 2;
    #pragma unroll
    for (int mt = 0; mt < 2; mt++) {
        #pragma unroll
        for (int nt = 0; nt < 4; nt++) {
            int col0 = wn + wnw + nt * 8 + tc;
            #pragma unroll
            for (int h = 0; h < 2; h++) {
                int row = gm + wm + mt * 16 + g + h * 8;
                if (row >= M) continue;
                float v0 = c[mt][nt][h * 2 + 0];
                float v1 = c[mt][nt][h * 2 + 1];
                if (MODE == 0) {
                    if (col0 < N)     out[(size_t)row * N + col0]     = v0 + __ldg(&bias[col0]);
                    if (col0 + 1 < N) out[(size_t)row * N + col0 + 1] = v1 + __ldg(&bias[col0 + 1]);
                } else {
                    v0 += __ldg(&bias[col0]);
                    v1 += __ldg(&bias[col0 + 1]);
                    if (MODE == 1) {
                        v0 = fmaxf(v0, 0.f);
                        v1 = fmaxf(v1, 0.f);
                    } else {
                        float s0 = __ldg(&gamma[col0]) * rsqrtf(__ldg(&rvar[col0]) + 1e-5f);
                        float s1 = __ldg(&gamma[col0 + 1]) * rsqrtf(__ldg(&rvar[col0 + 1]) + 1e-5f);
                        float p0 = v0 * s0 + (__ldg(&beta[col0]) - __ldg(&rmean[col0]) * s0);
                        float p1 = v1 * s1 + (__ldg(&beta[col0 + 1]) - __ldg(&rmean[col0 + 1]) * s1);
                        preout[(size_t)row * N + col0]     = p0;
                        preout[(size_t)row * N + col0 + 1] = p1;
                        v0 = tanhf(p0);
                        v1 = tanhf(p1);
                    }
                    size_t o = (size_t)row * N + col0;
                    out[o] = v0;
                    out[o + 1] = v1;
                    *(uint32_t*)(outh + o) = pack_hi(v0, v1);
                    *(uint32_t*)(outl + o) = pack_lo(v0, v1);
                }
            }
        }
    }
}

// ---------------- true_lab ----------------
__global__ void truelab_k(const float* __restrict__ wtl, const float* __restrict__ btl,
                          float* __restrict__ out) {
    int warp = (blockIdx.x * blockDim.x + threadIdx.x) >> 5;
    int lane = threadIdx.x & 31;
    if (warp >= NN) return;
    const float* p = g_prebn + (size_t)warp * NBITS;
    float s = p[lane] * wtl[lane] + p[lane + 32] * wtl[lane + 32];
    #pragma unroll
    for (int o = 16; o > 0; o >>= 1) s += __shfl_down_sync(0xffffffffu, s, o);
    if (lane == 0) out[warp] = s + btl[0];
}

// ---------------- launch ----------------
extern "C" void kernel_launch(void* const* d_in, const int* in_sizes, int n_in,
                              void* d_out, int out_size)
{
    const float* features = (const float*)d_in[0];
    const int*   edges    = (const int*)d_in[1];
    const float* w1l = (const float*)d_in[2];
    const float* b1l = (const float*)d_in[3];
    const float* w1r = (const float*)d_in[4];
    const float* w2l = (const float*)d_in[5];
    const float* b2l = (const float*)d_in[6];
    const float* w2r = (const float*)d_in[7];
    const float* whd = (const float*)d_in[8];
    const float* bhd = (const float*)d_in[9];
    const float* wclas = (const float*)d_in[10];
    const float* bclas = (const float*)d_in[11];
    const float* wconv = (const float*)d_in[12];
    const float* bconv = (const float*)d_in[13];
    const float* gamma = (const float*)d_in[14];
    const float* beta  = (const float*)d_in[15];
    const float* rm    = (const float*)d_in[16];
    const float* rv    = (const float*)d_in[17];
    const float* wtl   = (const float*)d_in[18];
    const float* btl   = (const float*)d_in[19];
    const float* wcv   = (const float*)d_in[20];
    const float* bcv   = (const float*)d_in[21];

    float* out = (float*)d_out;
    float* o_logists = out;
    float* o_out     = out + (size_t)NN * NCLS;
    float* o_fealab  = o_out + (size_t)NN * NBITS;
    float* o_feacv   = o_fealab + (size_t)NN * HDIM;
    float* o_truelab = o_feacv + (size_t)NN * NCLS;

    const int* esrc = edges;
    const int* edst = edges + NE;

    float *p_h1f, *p_pre;
    __nv_bfloat16 *p_fh, *p_fl, *p_mh, *p_ml, *p_h1h, *p_h1l, *p_h2h, *p_h2l, *p_oh, *p_ol, *p_wth, *p_wtl;
    cudaGetSymbolAddress((void**)&p_h1f, g_h1f);
    cudaGetSymbolAddress((void**)&p_pre, g_prebn);
    cudaGetSymbolAddress((void**)&p_fh, g_fh);
    cudaGetSymbolAddress((void**)&p_fl, g_fl);
    cudaGetSymbolAddress((void**)&p_mh, g_mh);
    cudaGetSymbolAddress((void**)&p_ml, g_ml);
    cudaGetSymbolAddress((void**)&p_h1h, g_h1h);
    cudaGetSymbolAddress((void**)&p_h1l, g_h1l);
    cudaGetSymbolAddress((void**)&p_h2h, g_h2h);
    cudaGetSymbolAddress((void**)&p_h2l, g_h2l);
    cudaGetSymbolAddress((void**)&p_oh, g_oh);
    cudaGetSymbolAddress((void**)&p_ol, g_ol);
    cudaGetSymbolAddress((void**)&p_wth, g_wth);
    cudaGetSymbolAddress((void**)&p_wtl, g_wtl);

    const int SM128 = (2 * 128 + 2 * 64) * 128 * 2;  // 98304
    const int SM64  = (2 * 128 + 2 * 64) * 64 * 2;   // 49152
    cudaFuncSetAttribute(mm_kernel<1, true, 128>,  cudaFuncAttributeMaxDynamicSharedMemorySize, SM128);
    cudaFuncSetAttribute(mm_kernel<0, false, 128>, cudaFuncAttributeMaxDynamicSharedMemorySize, SM128);
    cudaFuncSetAttribute(mm_kernel<2, false, 128>, cudaFuncAttributeMaxDynamicSharedMemorySize, SM128);
    cudaFuncSetAttribute(mm_kernel<0, false, 64>,  cudaFuncAttributeMaxDynamicSharedMemorySize, SM64);

    // operand prep (independent of CSR)
    conv_k<<<(NN * FD / 4 + 255) / 256, 256>>>(features, p_fh, p_fl, NN * FD / 4);
    wpackT_k<<<(128 * 16 + 255) / 256, 256>>>(w1l, p_wth + WT_W1L, p_wtl + WT_W1L, 128, 128);
    wpackT_k<<<(128 * 16 + 255) / 256, 256>>>(w1r, p_wth + WT_W1R, p_wtl + WT_W1R, 128, 128);
    wpackT_k<<<(128 * 16 + 255) / 256, 256>>>(w2l, p_wth + WT_W2L, p_wtl + WT_W2L, 128, 128);
    wpackT_k<<<(128 * 16 + 255) / 256, 256>>>(w2r, p_wth + WT_W2R, p_wtl + WT_W2R, 128, 128);
    wpackT_k<<<(300 * 16 + 255) / 256, 256>>>(whd, p_wth + WT_WHD, p_wtl + WT_WHD, 128, 300);
    wpackT_k<<<(100 * 16 + 255) / 256, 256>>>(wclas, p_wth + WT_WCLAS, p_wtl + WT_WCLAS, 128, 100);
    wpackT_k<<<(64 * 16 + 255) / 256, 256>>>(wconv, p_wth + WT_WCONV, p_wtl + WT_WCONV, 128, 64);
    wpackT_k<<<(100 * 8 + 255) / 256, 256>>>(wcv, p_wth + WT_WCV, p_wtl + WT_WCV, 64, 100);

    // CSR build
    zero_k<<<(NN + 255) / 256, 256>>>();
    hist_k<<<512, 256>>>(edst);
    scan_all_k<<<1, 1024>>>();
    scatter_k<<<512, 256>>>(esrc, edst);

    const int AGG_BLOCKS = (NN * 32 + 255) / 256;
    const int GM = (NN + 127) / 128;  // 391

    // layer 1
    agg_k<<<AGG_BLOCKS, 256>>>(features, p_mh, p_ml);
    mm_kernel<1, true, 128><<<dim3(GM, 2), 256, SM128>>>(
        p_mh, p_ml, p_fh, p_fl,
        p_wth + WT_W1L, p_wtl + WT_W1L, p_wth + WT_W1R, p_wtl + WT_W1R,
        b1l, p_h1f, p_h1h, p_h1l, NN, FD,
        nullptr, nullptr, nullptr, nullptr, nullptr);
    // layer 2
    agg_k<<<AGG_BLOCKS, 256>>>(p_h1f, p_mh, p_ml);
    mm_kernel<1, true, 128><<<dim3(GM, 2), 256, SM128>>>(
        p_mh, p_ml, p_h1h, p_h1l,
        p_wth + WT_W2L, p_wtl + WT_W2L, p_wth + WT_W2R, p_wtl + WT_W2R,
        b2l, p_h1f, p_h2h, p_h2l, NN, FD,
        nullptr, nullptr, nullptr, nullptr, nullptr);

    // heads
    mm_kernel<0, false, 128><<<dim3(GM, (HDIM + 63) / 64), 256, SM128>>>(
        p_h2h, p_h2l, nullptr, nullptr,
        p_wth + WT_WHD, p_wtl + WT_WHD, nullptr, nullptr,
        bhd, o_fealab, nullptr, nullptr, NN, HDIM,
        nullptr, nullptr, nullptr, nullptr, nullptr);
    mm_kernel<0, false, 128><<<dim3(GM, (NCLS + 63) / 64), 256, SM128>>>(
        p_h2h, p_h2l, nullptr, nullptr,
        p_wth + WT_WCLAS, p_wtl + WT_WCLAS, nullptr, nullptr,
        bclas, o_logists, nullptr, nullptr, NN, NCLS,
        nullptr, nullptr, nullptr, nullptr, nullptr);
    mm_kernel<2, false, 128><<<dim3(GM, 1), 256, SM128>>>(
        p_h2h, p_h2l, nullptr, nullptr,
        p_wth + WT_WCONV, p_wtl + WT_WCONV, nullptr, nullptr,
        bconv, o_out, p_oh, p_ol, NN, NBITS,
        gamma, beta, rm, rv, p_pre);
    mm_kernel<0, false, 64><<<dim3(GM, (NCLS + 63) / 64), 256, SM64>>>(
        p_oh, p_ol, nullptr, nullptr,
        p_wth + WT_WCV, p_wtl + WT_WCV, nullptr, nullptr,
        bcv, o_feacv, nullptr, nullptr, NN, NCLS,
        nullptr, nullptr, nullptr, nullptr, nullptr);
    truelab_k<<<(NN * 32 + 255) / 256, 256>>>(wtl, btl, o_truelab);
}

// round 7
// speedup vs baseline: 1.1010x; 1.1010x over previous
#include <cuda_runtime.h>
#include <cuda_bf16.h>
#include <cstdint>

#define NN 50000
#define NE 800000
#define FD 128
#define NBITS 64
#define NCLS 100
#define HDIM 300

// ---------------- scratch (device globals: allocation-free) ----------------
__device__ int   g_cursor[NN];
__device__ int   g_rowptr[NN + 1];
__device__ int   g_col[NE];
__device__ float g_h1f[NN * FD];           // fp32 h1 (for layer-2 aggregation)

// bf16 hi/lo operand planes
__device__ __nv_bfloat16 g_fh[NN * FD],  g_fl[NN * FD];      // features
__device__ __nv_bfloat16 g_mh[NN * FD],  g_ml[NN * FD];      // mean (both layers)
__device__ __nv_bfloat16 g_h1h[NN * FD], g_h1l[NN * FD];     // h1
__device__ __nv_bfloat16 g_h2h[NN * FD], g_h2l[NN * FD];     // h2
__device__ __nv_bfloat16 g_oh[NN * NBITS], g_ol[NN * NBITS]; // tanh out

// weight planes (transposed [N x K]); heads packed into one [512 x 128]
#define WT_W1L   0
#define WT_W1R   16384
#define WT_W2L   32768
#define WT_W2R   49152
#define WT_HEADS 65536        /* rows 0-319 whd(pad), 320-447 wclas(pad), 448-511 wconv */
#define WT_WCV   131072       /* 100 x 64 */
#define WT_TOTAL 137472
__device__ __nv_bfloat16 g_wth[WT_TOTAL], g_wtl[WT_TOTAL];
__device__ float g_biascat[512];

// ---------------- helpers ----------------
__device__ __forceinline__ uint32_t smem_u32(const void* p) {
    uint32_t a;
    asm("{ .reg .u64 t; cvta.to.shared.u64 t, %1; cvt.u32.u64 %0, t; }" : "=r"(a) : "l"(p));
    return a;
}
__device__ __forceinline__ void cpa16(uint32_t dst, const void* src, int sz) {
    asm volatile("cp.async.ca.shared.global [%0], [%1], 16, %2;"
                 :: "r"(dst), "l"(src), "r"(sz));
}
__device__ __forceinline__ void cpa_wait() {
    asm volatile("cp.async.commit_group;\n\tcp.async.wait_group 0;" ::: "memory");
}
__device__ __forceinline__ void ldsm4(uint32_t& r0, uint32_t& r1, uint32_t& r2, uint32_t& r3,
                                      uint32_t addr) {
    asm volatile("ldmatrix.sync.aligned.m8n8.x4.shared.b16 {%0,%1,%2,%3}, [%4];"
                 : "=r"(r0), "=r"(r1), "=r"(r2), "=r"(r3) : "r"(addr));
}
__device__ __forceinline__ void mma16816(float* c, uint32_t a0, uint32_t a1, uint32_t a2,
                                         uint32_t a3, uint32_t b0, uint32_t b1) {
    asm volatile("mma.sync.aligned.m16n8k16.row.col.f32.bf16.bf16.f32 "
                 "{%0,%1,%2,%3},{%4,%5,%6,%7},{%8,%9},{%0,%1,%2,%3};"
                 : "+f"(c[0]), "+f"(c[1]), "+f"(c[2]), "+f"(c[3])
                 : "r"(a0), "r"(a1), "r"(a2), "r"(a3), "r"(b0), "r"(b1));
}
template <int RB>
__device__ __forceinline__ int swoff(int row, int k) {
    return row * RB + (((k >> 3) ^ (row & 7)) << 4) + ((k & 7) << 1);
}
__device__ __forceinline__ uint32_t pack_hi(float x, float y) {
    __nv_bfloat162 t = __floats2bfloat162_rn(x, y);
    return *(uint32_t*)&t;
}
__device__ __forceinline__ uint32_t pack_lo(float x, float y) {
    float hx = __bfloat162float(__float2bfloat16(x));
    float hy = __bfloat162float(__float2bfloat16(y));
    __nv_bfloat162 t = __floats2bfloat162_rn(x - hx, y - hy);
    return *(uint32_t*)&t;
}
// pack 8 k-values of column n of src [Kd x Nd] into dst planes
__device__ __forceinline__ void pack8(const float* __restrict__ s, int Nd, int n, int k0,
                                      __nv_bfloat16* dh, __nv_bfloat16* dl, bool valid) {
    uint32_t h[4] = {0, 0, 0, 0}, l[4] = {0, 0, 0, 0};
    if (valid) {
        #pragma unroll
        for (int q = 0; q < 4; q++) {
            float v0 = s[(size_t)(k0 + 2 * q) * Nd + n];
            float v1 = s[(size_t)(k0 + 2 * q + 1) * Nd + n];
            h[q] = pack_hi(v0, v1);
            l[q] = pack_lo(v0, v1);
        }
    }
    *(uint4*)dh = *(uint4*)h;
    *(uint4*)dl = *(uint4*)l;
}

// ---------------- prep: feature planes + all weight packs + zero + bias concat ------
#define PB_FEAT  6250
#define PB_ZERO  (PB_FEAT + 196)     /* 6446 */
#define PB_WLYR  (PB_ZERO + 32)      /* 6478 */
#define PB_WHD   (PB_WLYR + 20)      /* 6498 */
#define PB_WCLAS (PB_WHD + 8)        /* 6506 */
#define PB_WCONV (PB_WCLAS + 4)      /* 6510 */
#define PB_WCV   (PB_WCONV + 4)      /* 6514 */
#define PB_TOTAL (PB_WCV + 2)        /* 6516 */

__global__ void prep_k(const float* __restrict__ feat,
                       const float* __restrict__ w1l, const float* __restrict__ w1r,
                       const float* __restrict__ w2l, const float* __restrict__ w2r,
                       const float* __restrict__ whd, const float* __restrict__ wclas,
                       const float* __restrict__ wconv, const float* __restrict__ wcv,
                       const float* __restrict__ bhd, const float* __restrict__ bclas,
                       const float* __restrict__ bconv)
{
    int b = blockIdx.x, tid = threadIdx.x;
    if (b < PB_FEAT) {
        int i = b * 256 + tid;   // exactly 1,600,000 items
        float4 v = ((const float4*)feat)[i];
        ((uint2*)g_fh)[i] = make_uint2(pack_hi(v.x, v.y), pack_hi(v.z, v.w));
        ((uint2*)g_fl)[i] = make_uint2(pack_lo(v.x, v.y), pack_lo(v.z, v.w));
    } else if (b < PB_ZERO) {
        int i = (b - PB_FEAT) * 256 + tid;
        if (i < NN) g_cursor[i] = 0;
    } else if (b < PB_WLYR) {
        int bb = b - PB_ZERO;
        int seg = bb >> 3;
        const float* src = seg == 0 ? w1l : seg == 1 ? w1r : seg == 2 ? w2l : w2r;
        int off = seg * 16384;
        int item = (bb & 7) * 256 + tid;          // < 2048
        int n = item >> 4, k0 = (item & 15) * 8;
        pack8(src, 128, n, k0, g_wth + off + n * 128 + k0, g_wtl + off + n * 128 + k0, true);
    } else if (b < PB_WHD) {
        int item = (b - PB_WLYR) * 256 + tid;     // < 5120 (320 rows)
        int n = item >> 4, k0 = (item & 15) * 8;
        pack8(whd, 300, n, k0, g_wth + WT_HEADS + n * 128 + k0,
              g_wtl + WT_HEADS + n * 128 + k0, n < 300);
    } else if (b < PB_WCLAS) {
        int item = (b - PB_WHD) * 256 + tid;      // < 2048 (128 rows)
        int n = item >> 4, k0 = (item & 15) * 8;
        int r = 320 + n;
        pack8(wclas, 100, n, k0, g_wth + WT_HEADS + r * 128 + k0,
              g_wtl + WT_HEADS + r * 128 + k0, n < 100);
    } else if (b < PB_WCONV) {
        int item = (b - PB_WCLAS) * 256 + tid;    // < 1024 (64 rows)
        int n = item >> 4, k0 = (item & 15) * 8;
        int r = 448 + n;
        pack8(wconv, 64, n, k0, g_wth + WT_HEADS + r * 128 + k0,
              g_wtl + WT_HEADS + r * 128 + k0, true);
    } else if (b < PB_WCV) {
        int item = (b - PB_WCONV) * 256 + tid;
        if (item < 800) {                          // 100 rows x 8 chunks (K=64)
            int n = item >> 3, k0 = (item & 7) * 8;
            pack8(wcv, 100, n, k0, g_wth + WT_WCV + n * 64 + k0,
                  g_wtl + WT_WCV + n * 64 + k0, true);
        }
    } else {
        int i = (b - PB_WCV) * 256 + tid;
        if (i < 512) {
            float v = (i < 300) ? bhd[i] : (i < 320) ? 0.f :
                      (i < 420) ? bclas[i - 320] : (i < 448) ? 0.f : bconv[i - 448];
            g_biascat[i] = v;
        }
    }
}

// ---------------- CSR build ----------------
__global__ void hist_k(const int* __restrict__ dst) {
    for (int e = blockIdx.x * blockDim.x + threadIdx.x; e < NE; e += gridDim.x * blockDim.x)
        atomicAdd(&g_cursor[dst[e]], 1);
}
__global__ void scan_all_k() {
    const int T = 1024;
    const int PER = (NN + T - 1) / T;   // 49
    int tid = threadIdx.x;
    int base = tid * PER;
    int lim = NN - base; if (lim < 0) lim = 0; if (lim > PER) lim = PER;
    int sum = 0;
    for (int j = 0; j < lim; j++) sum += g_cursor[base + j];
    int lane = tid & 31, w = tid >> 5;
    int x = sum;
    #pragma unroll
    for (int o = 1; o < 32; o <<= 1) {
        int y = __shfl_up_sync(0xffffffffu, x, o);
        if (lane >= o) x += y;
    }
    __shared__ int ws[32];
    if (lane == 31) ws[w] = x;
    __syncthreads();
    if (w == 0) {
        int s = ws[lane];
        #pragma unroll
        for (int o = 1; o < 32; o <<= 1) {
            int y = __shfl_up_sync(0xffffffffu, s, o);
            if (lane >= o) s += y;
        }
        ws[lane] = s;
    }
    __syncthreads();
    int run = x - sum + (w > 0 ? ws[w - 1] : 0);
    for (int j = 0; j < lim; j++) {
        int i = base + j;
        int cnt = g_cursor[i];
        g_rowptr[i] = run;
        g_cursor[i] = run;
        run += cnt;
    }
    if (tid == 0) g_rowptr[NN] = NE;
}
__global__ void scatter_k(const int* __restrict__ src, const int* __restrict__ dst) {
    for (int e = blockIdx.x * blockDim.x + threadIdx.x; e < NE; e += gridDim.x * blockDim.x) {
        int pos = atomicAdd(&g_cursor[dst[e]], 1);
        g_col[pos] = src[e];
    }
}

// ---------------- mean aggregation ----------------
__global__ void agg_k(const float* __restrict__ x, __nv_bfloat16* __restrict__ mh,
                      __nv_bfloat16* __restrict__ ml) {
    int warp = blockIdx.x * (blockDim.x >> 5) + (threadIdx.x >> 5);
    int lane = threadIdx.x & 31;
    if (warp >= NN) return;
    int beg = g_rowptr[warp], end = g_rowptr[warp + 1];
    float4 acc = make_float4(0.f, 0.f, 0.f, 0.f);
    for (int e = beg; e < end; ++e) {
        int s = __ldg(&g_col[e]);
        float4 v = *(const float4*)(x + (size_t)s * FD + lane * 4);
        acc.x += v.x; acc.y += v.y; acc.z += v.z; acc.w += v.w;
    }
    float sc = 1.f / (float)max(end - beg, 1);
    float r0 = acc.x * sc, r1 = acc.y * sc, r2 = acc.z * sc, r3 = acc.w * sc;
    size_t o = (size_t)warp * FD + lane * 4;
    *(uint2*)(mh + o) = make_uint2(pack_hi(r0, r1), pack_hi(r2, r3));
    *(uint2*)(ml + o) = make_uint2(pack_lo(r0, r1), pack_lo(r2, r3));
}

// ---------------- generic bf16-split GEMM (layers + feacv) ----------------
template <bool DUAL, bool RELU, bool WF32, bool WPLANES, int K>
__global__ void __launch_bounds__(256)
mm_kernel(const __nv_bfloat16* __restrict__ A1h, const __nv_bfloat16* __restrict__ A1l,
          const __nv_bfloat16* __restrict__ A2h, const __nv_bfloat16* __restrict__ A2l,
          const __nv_bfloat16* __restrict__ W1h, const __nv_bfloat16* __restrict__ W1l,
          const __nv_bfloat16* __restrict__ W2h, const __nv_bfloat16* __restrict__ W2l,
          const float* __restrict__ bias, float* __restrict__ outf,
          __nv_bfloat16* __restrict__ outh, __nv_bfloat16* __restrict__ outl,
          int M, int N)
{
    constexpr int RB  = K * 2;
    constexpr int ATB = 128 * RB;
    constexpr int BTB = 64 * RB;
    constexpr int CH  = K / 8;
    extern __shared__ __align__(16) char smem[];
    uint32_t sbase = smem_u32(smem);
    uint32_t sAhi = sbase, sAlo = sbase + ATB, sBhi = sbase + 2 * ATB, sBlo = sbase + 2 * ATB + BTB;

    int tid = threadIdx.x, lane = tid & 31, wid = tid >> 5;
    int wm  = (wid & 3) * 32;
    int wnw = (wid >> 2) * 32;
    int gm  = blockIdx.x * 128;
    int wn  = blockIdx.y * 64;

    float c[2][4][4];
    #pragma unroll
    for (int i = 0; i < 2; i++)
        #pragma unroll
        for (int j = 0; j < 4; j++)
            #pragma unroll
            for (int q = 0; q < 4; q++) c[i][j][q] = 0.f;

    int a_row = (lane & 15);
    int a_kof = (lane >> 1) & 8;
    int b_row = (lane & 7) + ((lane >> 1) & 8);
    int b_kof = lane & 8;

    const int npair = DUAL ? 2 : 1;
    for (int pair = 0; pair < npair; ++pair) {
        const __nv_bfloat16* Ah = pair ? A2h : A1h;
        const __nv_bfloat16* Al = pair ? A2l : A1l;
        const __nv_bfloat16* Wh = pair ? W2h : W1h;
        const __nv_bfloat16* Wl = pair ? W2l : W1l;

        #pragma unroll 2
        for (int cc = tid; cc < 128 * CH; cc += 256) {
            int row = cc / CH, ch = cc - row * CH;
            int grow = gm + row;
            int sz = (grow < M) ? 16 : 0;
            uint32_t doff = (uint32_t)(row * RB + ((ch ^ (row & 7)) << 4));
            size_t so = (size_t)grow * K + ch * 8;
            cpa16(sAhi + doff, Ah + so, sz);
            cpa16(sAlo + doff, Al + so, sz);
        }
        #pragma unroll 2
        for (int cc = tid; cc < 64 * CH; cc += 256) {
            int n = cc / CH, ch = cc - n * CH;
            int gn = wn + n;
            int sz = (gn < N) ? 16 : 0;
            uint32_t doff = (uint32_t)(n * RB + ((ch ^ (n & 7)) << 4));
            size_t so = (size_t)gn * K + ch * 8;
            cpa16(sBhi + doff, Wh + so, sz);
            cpa16(sBlo + doff, Wl + so, sz);
        }
        cpa_wait();
        __syncthreads();

        #pragma unroll
        for (int k0 = 0; k0 < K; k0 += 16) {
            uint32_t ah[2][4], al[2][4], bh[4][2], bl[4][2];
            #pragma unroll
            for (int mt = 0; mt < 2; mt++) {
                int oh = swoff<RB>(wm + mt * 16 + a_row, k0 + a_kof);
                ldsm4(ah[mt][0], ah[mt][1], ah[mt][2], ah[mt][3], sAhi + oh);
                ldsm4(al[mt][0], al[mt][1], al[mt][2], al[mt][3], sAlo + oh);
            }
            #pragma unroll
            for (int g = 0; g < 2; g++) {
                int ob = swoff<RB>(wnw + g * 16 + b_row, k0 + b_kof);
                ldsm4(bh[g * 2][0], bh[g * 2][1], bh[g * 2 + 1][0], bh[g * 2 + 1][1], sBhi + ob);
                ldsm4(bl[g * 2][0], bl[g * 2][1], bl[g * 2 + 1][0], bl[g * 2 + 1][1], sBlo + ob);
            }
            #pragma unroll
            for (int mt = 0; mt < 2; mt++)
                #pragma unroll
                for (int nt = 0; nt < 4; nt++) {
                    mma16816(c[mt][nt], ah[mt][0], ah[mt][1], ah[mt][2], ah[mt][3],
                             bh[nt][0], bh[nt][1]);
                    mma16816(c[mt][nt], ah[mt][0], ah[mt][1], ah[mt][2], ah[mt][3],
                             bl[nt][0], bl[nt][1]);
                    mma16816(c[mt][nt], al[mt][0], al[mt][1], al[mt][2], al[mt][3],
                             bh[nt][0], bh[nt][1]);
                }
        }
        __syncthreads();
    }

    int g  = lane >> 2;
    int tc = (lane & 3) * 2;
    #pragma unroll
    for (int mt = 0; mt < 2; mt++) {
        #pragma unroll
        for (int nt = 0; nt < 4; nt++) {
            int col0 = wn + wnw + nt * 8 + tc;
            #pragma unroll
            for (int h = 0; h < 2; h++) {
                int row = gm + wm + mt * 16 + g + h * 8;
                if (row >= M) continue;
                float v0 = c[mt][nt][h * 2 + 0] + __ldg(&bias[col0 < N ? col0 : 0]);
                float v1 = c[mt][nt][h * 2 + 1] + __ldg(&bias[col0 + 1 < N ? col0 + 1 : 0]);
                if (RELU) { v0 = fmaxf(v0, 0.f); v1 = fmaxf(v1, 0.f); }
                size_t o = (size_t)row * N + col0;
                if (col0 + 1 < N) {
                    if (WF32) { outf[o] = v0; outf[o + 1] = v1; }
                    if (WPLANES) {
                        *(uint32_t*)(outh + o) = pack_hi(v0, v1);
                        *(uint32_t*)(outl + o) = pack_lo(v0, v1);
                    }
                } else if (col0 < N) {
                    if (WF32) outf[o] = v0;
                    if (WPLANES) { outh[o] = __float2bfloat16(v0);
                                   outl[o] = __float2bfloat16(v0 - __bfloat162float(__float2bfloat16(v0))); }
                }
            }
        }
    }
}

// ---------------- fused heads GEMM: fealab + logists + BN/tanh/conv + truelab -------
__global__ void __launch_bounds__(256)
heads_k(const __nv_bfloat16* __restrict__ Ah, const __nv_bfloat16* __restrict__ Al,
        float* __restrict__ o_fealab, float* __restrict__ o_logists,
        float* __restrict__ o_out, __nv_bfloat16* __restrict__ outh,
        __nv_bfloat16* __restrict__ outl, float* __restrict__ o_truelab,
        const float* __restrict__ gamma, const float* __restrict__ beta,
        const float* __restrict__ rmean, const float* __restrict__ rvar,
        const float* __restrict__ wtlin, const float* __restrict__ btl, int M)
{
    constexpr int K = 128, RB = 256, ATB = 128 * RB, BTB = 64 * RB, CH = 16;
    extern __shared__ __align__(16) char smem[];
    uint32_t sbase = smem_u32(smem);
    uint32_t sAhi = sbase, sAlo = sbase + ATB, sBhi = sbase + 2 * ATB, sBlo = sbase + 2 * ATB + BTB;

    int tid = threadIdx.x, lane = tid & 31, wid = tid >> 5;
    int wm  = (wid & 3) * 32;
    int wnw = (wid >> 2) * 32;
    int gm  = blockIdx.x * 128;
    int y   = blockIdx.y;
    int wn  = y * 64;
    int seg = (y < 5) ? 0 : (y < 7) ? 1 : 2;

    float c[2][4][4];
    #pragma unroll
    for (int i = 0; i < 2; i++)
        #pragma unroll
        for (int j = 0; j < 4; j++)
            #pragma unroll
            for (int q = 0; q < 4; q++) c[i][j][q] = 0.f;

    int a_row = (lane & 15);
    int a_kof = (lane >> 1) & 8;
    int b_row = (lane & 7) + ((lane >> 1) & 8);
    int b_kof = lane & 8;

    const __nv_bfloat16* Wh = g_wth + WT_HEADS;
    const __nv_bfloat16* Wl = g_wtl + WT_HEADS;

    #pragma unroll 2
    for (int cc = tid; cc < 128 * CH; cc += 256) {
        int row = cc / CH, ch = cc - row * CH;
        int grow = gm + row;
        int sz = (grow < M) ? 16 : 0;
        uint32_t doff = (uint32_t)(row * RB + ((ch ^ (row & 7)) << 4));
        size_t so = (size_t)grow * K + ch * 8;
        cpa16(sAhi + doff, Ah + so, sz);
        cpa16(sAlo + doff, Al + so, sz);
    }
    #pragma unroll 2
    for (int cc = tid; cc < 64 * CH; cc += 256) {
        int n = cc / CH, ch = cc - n * CH;
        int gn = wn + n;
        uint32_t doff = (uint32_t)(n * RB + ((ch ^ (n & 7)) << 4));
        size_t so = (size_t)gn * K + ch * 8;
        cpa16(sBhi + doff, Wh + so, 16);
        cpa16(sBlo + doff, Wl + so, 16);
    }
    cpa_wait();
    __syncthreads();

    #pragma unroll
    for (int k0 = 0; k0 < K; k0 += 16) {
        uint32_t ah[2][4], al[2][4], bh[4][2], bl[4][2];
        #pragma unroll
        for (int mt = 0; mt < 2; mt++) {
            int oh = swoff<RB>(wm + mt * 16 + a_row, k0 + a_kof);
            ldsm4(ah[mt][0], ah[mt][1], ah[mt][2], ah[mt][3], sAhi + oh);
            ldsm4(al[mt][0], al[mt][1], al[mt][2], al[mt][3], sAlo + oh);
        }
        #pragma unroll
        for (int g = 0; g < 2; g++) {
            int ob = swoff<RB>(wnw + g * 16 + b_row, k0 + b_kof);
            ldsm4(bh[g * 2][0], bh[g * 2][1], bh[g * 2 + 1][0], bh[g * 2 + 1][1], sBhi + ob);
            ldsm4(bl[g * 2][0], bl[g * 2][1], bl[g * 2 + 1][0], bl[g * 2 + 1][1], sBlo + ob);
        }
        #pragma unroll
        for (int mt = 0; mt < 2; mt++)
            #pragma unroll
            for (int nt = 0; nt < 4; nt++) {
                mma16816(c[mt][nt], ah[mt][0], ah[mt][1], ah[mt][2], ah[mt][3],
                         bh[nt][0], bh[nt][1]);
                mma16816(c[mt][nt], ah[mt][0], ah[mt][1], ah[mt][2], ah[mt][3],
                         bl[nt][0], bl[nt][1]);
                mma16816(c[mt][nt], al[mt][0], al[mt][1], al[mt][2], al[mt][3],
                         bh[nt][0], bh[nt][1]);
            }
    }
    __syncthreads();

    int g  = lane >> 2;
    int tc = (lane & 3) * 2;
    float rsum[2][2] = {{0.f, 0.f}, {0.f, 0.f}};

    #pragma unroll
    for (int mt = 0; mt < 2; mt++) {
        #pragma unroll
        for (int nt = 0; nt < 4; nt++) {
            int gcol0 = wn + wnw + nt * 8 + tc;   // 0..511 packed col
            #pragma unroll
            for (int h = 0; h < 2; h++) {
                int row = gm + wm + mt * 16 + g + h * 8;
                if (row >= M) continue;
                float v0 = c[mt][nt][h * 2 + 0] + __ldg(&g_biascat[gcol0]);
                float v1 = c[mt][nt][h * 2 + 1] + __ldg(&g_biascat[gcol0 + 1]);
                if (seg == 2) {
                    int l0 = gcol0 - 448;
                    float s0 = __ldg(&gamma[l0]) * rsqrtf(__ldg(&rvar[l0]) + 1e-5f);
                    float s1 = __ldg(&gamma[l0 + 1]) * rsqrtf(__ldg(&rvar[l0 + 1]) + 1e-5f);
                    float p0 = v0 * s0 + (__ldg(&beta[l0]) - __ldg(&rmean[l0]) * s0);
                    float p1 = v1 * s1 + (__ldg(&beta[l0 + 1]) - __ldg(&rmean[l0 + 1]) * s1);
                    float t0 = tanhf(p0), t1 = tanhf(p1);
                    size_t o = (size_t)row * NBITS + l0;
                    o_out[o] = t0; o_out[o + 1] = t1;
                    *(uint32_t*)(outh + o) = pack_hi(t0, t1);
                    *(uint32_t*)(outl + o) = pack_lo(t0, t1);
                    rsum[mt][h] += p0 * __ldg(&wtlin[l0]) + p1 * __ldg(&wtlin[l0 + 1]);
                } else if (seg == 0) {
                    int l0 = gcol0;
                    if (l0 < 300)     o_fealab[(size_t)row * 300 + l0] = v0;
                    if (l0 + 1 < 300) o_fealab[(size_t)row * 300 + l0 + 1] = v1;
                } else {
                    int l0 = gcol0 - 320;
                    if (l0 < 100)     o_logists[(size_t)row * 100 + l0] = v0;
                    if (l0 + 1 < 100) o_logists[(size_t)row * 100 + l0 + 1] = v1;
                }
            }
        }
    }

    if (seg == 2) {
        // reduce rsum over the 4 tc-lanes, then across the two warp-column groups
        float* tl = (float*)smem;   // [128][2]
        #pragma unroll
        for (int mt = 0; mt < 2; mt++)
            #pragma unroll
            for (int h = 0; h < 2; h++) {
                float s = rsum[mt][h];
                s += __shfl_xor_sync(0xffffffffu, s, 1);
                s += __shfl_xor_sync(0xffffffffu, s, 2);
                rsum[mt][h] = s;
            }
        __syncthreads();
        if ((lane & 3) == 0) {
            #pragma unroll
            for (int mt = 0; mt < 2; mt++)
                #pragma unroll
                for (int h = 0; h < 2; h++) {
                    int r = wm + mt * 16 + g + h * 8;
                    tl[r * 2 + (wnw >> 5)] = rsum[mt][h];
                }
        }
        __syncthreads();
        if (tid < 128) {
            int row = gm + tid;
            if (row < M) o_truelab[row] = tl[tid * 2] + tl[tid * 2 + 1] + __ldg(&btl[0]);
        }
    }
}

// ---------------- launch ----------------
extern "C" void kernel_launch(void* const* d_in, const int* in_sizes, int n_in,
                              void* d_out, int out_size)
{
    const float* features = (const float*)d_in[0];
    const int*   edges    = (const int*)d_in[1];
    const float* w1l = (const float*)d_in[2];
    const float* b1l = (const float*)d_in[3];
    const float* w1r = (const float*)d_in[4];
    const float* w2l = (const float*)d_in[5];
    const float* b2l = (const float*)d_in[6];
    const float* w2r = (const float*)d_in[7];
    const float* whd = (const float*)d_in[8];
    const float* bhd = (const float*)d_in[9];
    const float* wclas = (const float*)d_in[10];
    const float* bclas = (const float*)d_in[11];
    const float* wconv = (const float*)d_in[12];
    const float* bconv = (const float*)d_in[13];
    const float* gamma = (const float*)d_in[14];
    const float* beta  = (const float*)d_in[15];
    const float* rm    = (const float*)d_in[16];
    const float* rv    = (const float*)d_in[17];
    const float* wtl   = (const float*)d_in[18];
    const float* btl   = (const float*)d_in[19];
    const float* wcv   = (const float*)d_in[20];
    const float* bcv   = (const float*)d_in[21];

    float* out = (float*)d_out;
    float* o_logists = out;
    float* o_out     = out + (size_t)NN * NCLS;
    float* o_fealab  = o_out + (size_t)NN * NBITS;
    float* o_feacv   = o_fealab + (size_t)NN * HDIM;
    float* o_truelab = o_feacv + (size_t)NN * NCLS;

    const int* esrc = edges;
    const int* edst = edges + NE;

    float* p_h1f;
    __nv_bfloat16 *p_fh, *p_fl, *p_mh, *p_ml, *p_h1h, *p_h1l, *p_h2h, *p_h2l, *p_oh, *p_ol, *p_wth, *p_wtl;
    cudaGetSymbolAddress((void**)&p_h1f, g_h1f);
    cudaGetSymbolAddress((void**)&p_fh, g_fh);
    cudaGetSymbolAddress((void**)&p_fl, g_fl);
    cudaGetSymbolAddress((void**)&p_mh, g_mh);
    cudaGetSymbolAddress((void**)&p_ml, g_ml);
    cudaGetSymbolAddress((void**)&p_h1h, g_h1h);
    cudaGetSymbolAddress((void**)&p_h1l, g_h1l);
    cudaGetSymbolAddress((void**)&p_h2h, g_h2h);
    cudaGetSymbolAddress((void**)&p_h2l, g_h2l);
    cudaGetSymbolAddress((void**)&p_oh, g_oh);
    cudaGetSymbolAddress((void**)&p_ol, g_ol);
    cudaGetSymbolAddress((void**)&p_wth, g_wth);
    cudaGetSymbolAddress((void**)&p_wtl, g_wtl);

    const int SM128 = (2 * 128 + 2 * 64) * 128 * 2;  // 98304
    const int SM64  = (2 * 128 + 2 * 64) * 64 * 2;   // 49152
    cudaFuncSetAttribute(mm_kernel<true, true, true, true, 128>,
                         cudaFuncAttributeMaxDynamicSharedMemorySize, SM128);
    cudaFuncSetAttribute(mm_kernel<true, true, false, true, 128>,
                         cudaFuncAttributeMaxDynamicSharedMemorySize, SM128);
    cudaFuncSetAttribute(mm_kernel<false, false, true, false, 64>,
                         cudaFuncAttributeMaxDynamicSharedMemorySize, SM64);
    cudaFuncSetAttribute(heads_k, cudaFuncAttributeMaxDynamicSharedMemorySize, SM128);

    // 0: prep (feature planes, weight packs, cursor zero, bias concat)
    prep_k<<<PB_TOTAL, 256>>>(features, w1l, w1r, w2l, w2r, whd, wclas, wconv, wcv,
                              bhd, bclas, bconv);
    // 1-3: CSR
    hist_k<<<512, 256>>>(edst);
    scan_all_k<<<1, 1024>>>();
    scatter_k<<<512, 256>>>(esrc, edst);

    const int AGG_BLOCKS = (NN * 32 + 255) / 256;
    const int GM = (NN + 127) / 128;  // 391

    // 4-5: layer 1
    agg_k<<<AGG_BLOCKS, 256>>>(features, p_mh, p_ml);
    mm_kernel<true, true, true, true, 128><<<dim3(GM, 2), 256, SM128>>>(
        p_mh, p_ml, p_fh, p_fl,
        p_wth + WT_W1L, p_wtl + WT_W1L, p_wth + WT_W1R, p_wtl + WT_W1R,
        b1l, p_h1f, p_h1h, p_h1l, NN, FD);
    // 6-7: layer 2 (fp32 output not needed)
    agg_k<<<AGG_BLOCKS, 256>>>(p_h1f, p_mh, p_ml);
    mm_kernel<true, true, false, true, 128><<<dim3(GM, 2), 256, SM128>>>(
        p_mh, p_ml, p_h1h, p_h1l,
        p_wth + WT_W2L, p_wtl + WT_W2L, p_wth + WT_W2R, p_wtl + WT_W2R,
        b2l, nullptr, p_h2h, p_h2l, NN, FD);

    // 8: fused heads (fealab + logists + BN/tanh + truelab)
    heads_k<<<dim3(GM, 8), 256, SM128>>>(
        p_h2h, p_h2l, o_fealab, o_logists, o_out, p_oh, p_ol, o_truelab,
        gamma, beta, rm, rv, wtl, btl, NN);

    // 9: fea_convert
    mm_kernel<false, false, true, false, 64><<<dim3(GM, 2), 256, SM64>>>(
        p_oh, p_ol, nullptr, nullptr,
        p_wth + WT_WCV, p_wtl + WT_WCV, nullptr, nullptr,
        bcv, o_feacv, nullptr, nullptr, NN, NCLS);
}

// round 8
// speedup vs baseline: 1.1545x; 1.0487x over previous
#include <cuda_runtime.h>
#include <cuda_bf16.h>
#include <cstdint>

#define NN 50000
#define NE 800000
#define FD 128
#define NBITS 64
#define NCLS 100
#define HDIM 300

// ---------------- scratch ----------------
__device__ int   g_cursor[NN];
__device__ int   g_rowptr[NN + 1];
__device__ int   g_col[NE];
__device__ float g_h1f[NN * FD];

// bf16 hi/lo planes (only for operands with reuse)
__device__ __nv_bfloat16 g_mh[NN * FD],  g_ml[NN * FD];      // mean (both layers)
__device__ __nv_bfloat16 g_h2h[NN * FD], g_h2l[NN * FD];     // h2 (read 8x by heads)
__device__ __nv_bfloat16 g_oh[NN * NBITS], g_ol[NN * NBITS]; // tanh out (read 2x)

// weight planes (transposed [N x K]); heads packed into one [512 x 128]
#define WT_W1L   0
#define WT_W1R   16384
#define WT_W2L   32768
#define WT_W2R   49152
#define WT_HEADS 65536
#define WT_WCV   131072
#define WT_TOTAL 137472
__device__ __nv_bfloat16 g_wth[WT_TOTAL], g_wtl[WT_TOTAL];
__device__ float g_biascat[512];

// ---------------- helpers ----------------
__device__ __forceinline__ uint32_t smem_u32(const void* p) {
    uint32_t a;
    asm("{ .reg .u64 t; cvta.to.shared.u64 t, %1; cvt.u32.u64 %0, t; }" : "=r"(a) : "l"(p));
    return a;
}
__device__ __forceinline__ void cpa16(uint32_t dst, const void* src, int sz) {
    asm volatile("cp.async.ca.shared.global [%0], [%1], 16, %2;"
                 :: "r"(dst), "l"(src), "r"(sz));
}
__device__ __forceinline__ void cpa_wait() {
    asm volatile("cp.async.commit_group;\n\tcp.async.wait_group 0;" ::: "memory");
}
__device__ __forceinline__ void ldsm4(uint32_t& r0, uint32_t& r1, uint32_t& r2, uint32_t& r3,
                                      uint32_t addr) {
    asm volatile("ldmatrix.sync.aligned.m8n8.x4.shared.b16 {%0,%1,%2,%3}, [%4];"
                 : "=r"(r0), "=r"(r1), "=r"(r2), "=r"(r3) : "r"(addr));
}
__device__ __forceinline__ void mma16816(float* c, uint32_t a0, uint32_t a1, uint32_t a2,
                                         uint32_t a3, uint32_t b0, uint32_t b1) {
    asm volatile("mma.sync.aligned.m16n8k16.row.col.f32.bf16.bf16.f32 "
                 "{%0,%1,%2,%3},{%4,%5,%6,%7},{%8,%9},{%0,%1,%2,%3};"
                 : "+f"(c[0]), "+f"(c[1]), "+f"(c[2]), "+f"(c[3])
                 : "r"(a0), "r"(a1), "r"(a2), "r"(a3), "r"(b0), "r"(b1));
}
template <int RB>
__device__ __forceinline__ int swoff(int row, int k) {
    return row * RB + (((k >> 3) ^ (row & 7)) << 4) + ((k & 7) << 1);
}
__device__ __forceinline__ uint32_t pack_hi(float x, float y) {
    __nv_bfloat162 t = __floats2bfloat162_rn(x, y);
    return *(uint32_t*)&t;
}
__device__ __forceinline__ uint32_t pack_lo(float x, float y) {
    float hx = __bfloat162float(__float2bfloat16(x));
    float hy = __bfloat162float(__float2bfloat16(y));
    __nv_bfloat162 t = __floats2bfloat162_rn(x - hx, y - hy);
    return *(uint32_t*)&t;
}
__device__ __forceinline__ void pack8(const float* __restrict__ s, int Nd, int n, int k0,
                                      __nv_bfloat16* dh, __nv_bfloat16* dl, bool valid) {
    uint32_t h[4] = {0, 0, 0, 0}, l[4] = {0, 0, 0, 0};
    if (valid) {
        #pragma unroll
        for (int q = 0; q < 4; q++) {
            float v0 = s[(size_t)(k0 + 2 * q) * Nd + n];
            float v1 = s[(size_t)(k0 + 2 * q + 1) * Nd + n];
            h[q] = pack_hi(v0, v1);
            l[q] = pack_lo(v0, v1);
        }
    }
    *(uint4*)dh = *(uint4*)h;
    *(uint4*)dl = *(uint4*)l;
}

// ---------------- prep: weight packs + cursor zero + bias concat ----------------
#define PB_ZERO  196
#define PB_WLYR  (PB_ZERO + 32)    /* 228 */
#define PB_WHD   (PB_WLYR + 20)    /* 248 */
#define PB_WCLAS (PB_WHD + 8)      /* 256 */
#define PB_WCONV (PB_WCLAS + 4)    /* 260 */
#define PB_WCV   (PB_WCONV + 4)    /* 264 */
#define PB_TOTAL (PB_WCV + 2)      /* 266 */

__global__ void prep_k(const float* __restrict__ w1l, const float* __restrict__ w1r,
                       const float* __restrict__ w2l, const float* __restrict__ w2r,
                       const float* __restrict__ whd, const float* __restrict__ wclas,
                       const float* __restrict__ wconv, const float* __restrict__ wcv,
                       const float* __restrict__ bhd, const float* __restrict__ bclas,
                       const float* __restrict__ bconv)
{
    int b = blockIdx.x, tid = threadIdx.x;
    if (b < PB_ZERO) {
        int i = b * 256 + tid;
        if (i < NN) g_cursor[i] = 0;
    } else if (b < PB_WLYR) {
        int bb = b - PB_ZERO;
        int seg = bb >> 3;
        const float* src = seg == 0 ? w1l : seg == 1 ? w1r : seg == 2 ? w2l : w2r;
        int off = seg * 16384;
        int item = (bb & 7) * 256 + tid;
        int n = item >> 4, k0 = (item & 15) * 8;
        pack8(src, 128, n, k0, g_wth + off + n * 128 + k0, g_wtl + off + n * 128 + k0, true);
    } else if (b < PB_WHD) {
        int item = (b - PB_WLYR) * 256 + tid;        // < 5120
        int n = item >> 4, k0 = (item & 15) * 8;
        pack8(whd, 300, n, k0, g_wth + WT_HEADS + n * 128 + k0,
              g_wtl + WT_HEADS + n * 128 + k0, n < 300);
    } else if (b < PB_WCLAS) {
        int item = (b - PB_WHD) * 256 + tid;         // < 2048
        int n = item >> 4, k0 = (item & 15) * 8;
        int r = 320 + n;
        pack8(wclas, 100, n, k0, g_wth + WT_HEADS + r * 128 + k0,
              g_wtl + WT_HEADS + r * 128 + k0, n < 100);
    } else if (b < PB_WCONV) {
        int item = (b - PB_WCLAS) * 256 + tid;       // < 1024
        int n = item >> 4, k0 = (item & 15) * 8;
        int r = 448 + n;
        pack8(wconv, 64, n, k0, g_wth + WT_HEADS + r * 128 + k0,
              g_wtl + WT_HEADS + r * 128 + k0, true);
    } else if (b < PB_WCV) {
        int item = (b - PB_WCONV) * 256 + tid;
        if (item < 800) {
            int n = item >> 3, k0 = (item & 7) * 8;
            pack8(wcv, 100, n, k0, g_wth + WT_WCV + n * 64 + k0,
                  g_wtl + WT_WCV + n * 64 + k0, true);
        }
    } else {
        int i = (b - PB_WCV) * 256 + tid;
        if (i < 512) {
            float v = (i < 300) ? bhd[i] : (i < 320) ? 0.f :
                      (i < 420) ? bclas[i - 320] : (i < 448) ? 0.f : bconv[i - 448];
            g_biascat[i] = v;
        }
    }
}

// ---------------- CSR build ----------------
__global__ void hist_k(const int* __restrict__ dst) {
    for (int e = blockIdx.x * blockDim.x + threadIdx.x; e < NE; e += gridDim.x * blockDim.x)
        atomicAdd(&g_cursor[dst[e]], 1);
}
__global__ void scan_all_k() {
    const int T = 1024;
    const int PER = (NN + T - 1) / T;
    int tid = threadIdx.x;
    int base = tid * PER;
    int lim = NN - base; if (lim < 0) lim = 0; if (lim > PER) lim = PER;
    int sum = 0;
    for (int j = 0; j < lim; j++) sum += g_cursor[base + j];
    int lane = tid & 31, w = tid >> 5;
    int x = sum;
    #pragma unroll
    for (int o = 1; o < 32; o <<= 1) {
        int y = __shfl_up_sync(0xffffffffu, x, o);
        if (lane >= o) x += y;
    }
    __shared__ int ws[32];
    if (lane == 31) ws[w] = x;
    __syncthreads();
    if (w == 0) {
        int s = ws[lane];
        #pragma unroll
        for (int o = 1; o < 32; o <<= 1) {
            int y = __shfl_up_sync(0xffffffffu, s, o);
            if (lane >= o) s += y;
        }
        ws[lane] = s;
    }
    __syncthreads();
    int run = x - sum + (w > 0 ? ws[w - 1] : 0);
    for (int j = 0; j < lim; j++) {
        int i = base + j;
        int cnt = g_cursor[i];
        g_rowptr[i] = run;
        g_cursor[i] = run;
        run += cnt;
    }
    if (tid == 0) g_rowptr[NN] = NE;
}
__global__ void scatter_k(const int* __restrict__ src, const int* __restrict__ dst) {
    for (int e = blockIdx.x * blockDim.x + threadIdx.x; e < NE; e += gridDim.x * blockDim.x) {
        int pos = atomicAdd(&g_cursor[dst[e]], 1);
        g_col[pos] = src[e];
    }
}

// ---------------- mean aggregation -> planes ----------------
__global__ void agg_k(const float* __restrict__ x, __nv_bfloat16* __restrict__ mh,
                      __nv_bfloat16* __restrict__ ml) {
    int warp = blockIdx.x * (blockDim.x >> 5) + (threadIdx.x >> 5);
    int lane = threadIdx.x & 31;
    if (warp >= NN) return;
    int beg = g_rowptr[warp], end = g_rowptr[warp + 1];
    float4 acc = make_float4(0.f, 0.f, 0.f, 0.f);
    for (int e = beg; e < end; ++e) {
        int s = __ldg(&g_col[e]);
        float4 v = *(const float4*)(x + (size_t)s * FD + lane * 4);
        acc.x += v.x; acc.y += v.y; acc.z += v.z; acc.w += v.w;
    }
    float sc = 1.f / (float)max(end - beg, 1);
    float r0 = acc.x * sc, r1 = acc.y * sc, r2 = acc.z * sc, r3 = acc.w * sc;
    size_t o = (size_t)warp * FD + lane * 4;
    *(uint2*)(mh + o) = make_uint2(pack_hi(r0, r1), pack_hi(r2, r3));
    *(uint2*)(ml + o) = make_uint2(pack_lo(r0, r1), pack_lo(r2, r3));
}

// ---------------- mainloop core (shared by all GEMMs) ----------------
template <int RB>
__device__ __forceinline__ void mainloop128(uint32_t sAhi, uint32_t sAlo,
                                            uint32_t sBhi, uint32_t sBlo,
                                            float c[2][4][4], int wm, int wnw,
                                            int a_row, int a_kof, int b_row, int b_kof,
                                            int K) {
    for (int k0 = 0; k0 < K; k0 += 16) {
        uint32_t ah[2][4], al[2][4], bh[4][2], bl[4][2];
        #pragma unroll
        for (int mt = 0; mt < 2; mt++) {
            int oh = swoff<RB>(wm + mt * 16 + a_row, k0 + a_kof);
            ldsm4(ah[mt][0], ah[mt][1], ah[mt][2], ah[mt][3], sAhi + oh);
            ldsm4(al[mt][0], al[mt][1], al[mt][2], al[mt][3], sAlo + oh);
        }
        #pragma unroll
        for (int g = 0; g < 2; g++) {
            int ob = swoff<RB>(wnw + g * 16 + b_row, k0 + b_kof);
            ldsm4(bh[g * 2][0], bh[g * 2][1], bh[g * 2 + 1][0], bh[g * 2 + 1][1], sBhi + ob);
            ldsm4(bl[g * 2][0], bl[g * 2][1], bl[g * 2 + 1][0], bl[g * 2 + 1][1], sBlo + ob);
        }
        #pragma unroll
        for (int mt = 0; mt < 2; mt++)
            #pragma unroll
            for (int nt = 0; nt < 4; nt++) {
                mma16816(c[mt][nt], ah[mt][0], ah[mt][1], ah[mt][2], ah[mt][3],
                         bh[nt][0], bh[nt][1]);
                mma16816(c[mt][nt], ah[mt][0], ah[mt][1], ah[mt][2], ah[mt][3],
                         bl[nt][0], bl[nt][1]);
                mma16816(c[mt][nt], al[mt][0], al[mt][1], al[mt][2], al[mt][3],
                         bh[nt][0], bh[nt][1]);
            }
    }
}

// ---------------- SAGE layer GEMM ----------------
// c = Af_fp32 @ Wf + mean_planes @ Wm + bias, relu
// WF32: write fp32 out; WPLANES: write hi/lo planes
template <bool WF32, bool WPLANES>
__global__ void __launch_bounds__(256)
mm_layer(const float* __restrict__ Af,
         const __nv_bfloat16* __restrict__ A1h, const __nv_bfloat16* __restrict__ A1l,
         const __nv_bfloat16* __restrict__ Wfh, const __nv_bfloat16* __restrict__ Wfl,
         const __nv_bfloat16* __restrict__ Wmh, const __nv_bfloat16* __restrict__ Wml,
         const float* __restrict__ bias, float* __restrict__ outf,
         __nv_bfloat16* __restrict__ outh, __nv_bfloat16* __restrict__ outl, int M)
{
    constexpr int K = 128, RB = 256, ATB = 128 * RB, BTB = 64 * RB, CH = 16;
    constexpr int N = 128;
    extern __shared__ __align__(16) char smem[];
    char* pA = smem;
    uint32_t sbase = smem_u32(smem);
    uint32_t sAhi = sbase, sAlo = sbase + ATB, sBhi = sbase + 2 * ATB, sBlo = sbase + 2 * ATB + BTB;

    int tid = threadIdx.x, lane = tid & 31, wid = tid >> 5;
    int wm  = (wid & 3) * 32;
    int wnw = (wid >> 2) * 32;
    int gm  = blockIdx.x * 128;
    int wn  = blockIdx.y * 64;

    float c[2][4][4];
    #pragma unroll
    for (int i = 0; i < 2; i++)
        #pragma unroll
        for (int j = 0; j < 4; j++)
            #pragma unroll
            for (int q = 0; q < 4; q++) c[i][j][q] = 0.f;

    int a_row = (lane & 15);
    int a_kof = (lane >> 1) & 8;
    int b_row = (lane & 7) + ((lane >> 1) & 8);
    int b_kof = lane & 8;

    // ---- phase F: Af fp32 inline-convert; B via cp.async (issued first) ----
    #pragma unroll 2
    for (int cc = tid; cc < 64 * CH; cc += 256) {
        int n = cc / CH, ch = cc - n * CH;
        uint32_t doff = (uint32_t)(n * RB + ((ch ^ (n & 7)) << 4));
        size_t so = (size_t)(wn + n) * K + ch * 8;
        cpa16(sBhi + doff, Wfh + so, 16);
        cpa16(sBlo + doff, Wfl + so, 16);
    }
    #pragma unroll 2
    for (int cc = tid; cc < 128 * CH; cc += 256) {
        int row = cc / CH, ch = cc - row * CH;
        int grow = gm + row;
        uint32_t hq[4] = {0, 0, 0, 0}, lq[4] = {0, 0, 0, 0};
        if (grow < M) {
            const float4* p = (const float4*)(Af + (size_t)grow * K + ch * 8);
            float4 f0 = p[0], f1 = p[1];
            hq[0] = pack_hi(f0.x, f0.y); hq[1] = pack_hi(f0.z, f0.w);
            hq[2] = pack_hi(f1.x, f1.y); hq[3] = pack_hi(f1.z, f1.w);
            lq[0] = pack_lo(f0.x, f0.y); lq[1] = pack_lo(f0.z, f0.w);
            lq[2] = pack_lo(f1.x, f1.y); lq[3] = pack_lo(f1.z, f1.w);
        }
        int doff = row * RB + ((ch ^ (row & 7)) << 4);
        *(uint4*)(pA + doff)       = *(uint4*)hq;
        *(uint4*)(pA + ATB + doff) = *(uint4*)lq;
    }
    cpa_wait();
    __syncthreads();
    mainloop128<RB>(sAhi, sAlo, sBhi, sBlo, c, wm, wnw, a_row, a_kof, b_row, b_kof, K);
    __syncthreads();

    // ---- phase M: mean planes + Wm via cp.async ----
    #pragma unroll 2
    for (int cc = tid; cc < 128 * CH; cc += 256) {
        int row = cc / CH, ch = cc - row * CH;
        int grow = gm + row;
        int sz = (grow < M) ? 16 : 0;
        uint32_t doff = (uint32_t)(row * RB + ((ch ^ (row & 7)) << 4));
        size_t so = (size_t)grow * K + ch * 8;
        cpa16(sAhi + doff, A1h + so, sz);
        cpa16(sAlo + doff, A1l + so, sz);
    }
    #pragma unroll 2
    for (int cc = tid; cc < 64 * CH; cc += 256) {
        int n = cc / CH, ch = cc - n * CH;
        uint32_t doff = (uint32_t)(n * RB + ((ch ^ (n & 7)) << 4));
        size_t so = (size_t)(wn + n) * K + ch * 8;
        cpa16(sBhi + doff, Wmh + so, 16);
        cpa16(sBlo + doff, Wml + so, 16);
    }
    cpa_wait();
    __syncthreads();
    mainloop128<RB>(sAhi, sAlo, sBhi, sBlo, c, wm, wnw, a_row, a_kof, b_row, b_kof, K);

    // ---- epilogue ----
    int g  = lane >> 2;
    int tc = (lane & 3) * 2;
    #pragma unroll
    for (int mt = 0; mt < 2; mt++) {
        #pragma unroll
        for (int nt = 0; nt < 4; nt++) {
            int col0 = wn + wnw + nt * 8 + tc;
            #pragma unroll
            for (int h = 0; h < 2; h++) {
                int row = gm + wm + mt * 16 + g + h * 8;
                if (row >= M) continue;
                float v0 = fmaxf(c[mt][nt][h * 2 + 0] + __ldg(&bias[col0]), 0.f);
                float v1 = fmaxf(c[mt][nt][h * 2 + 1] + __ldg(&bias[col0 + 1]), 0.f);
                size_t o = (size_t)row * N + col0;
                if (WF32) { outf[o] = v0; outf[o + 1] = v1; }
                if (WPLANES) {
                    *(uint32_t*)(outh + o) = pack_hi(v0, v1);
                    *(uint32_t*)(outl + o) = pack_lo(v0, v1);
                }
            }
        }
    }
}

// ---------------- generic plane GEMM (feacv) ----------------
template <int K>
__global__ void __launch_bounds__(256)
mm_kernel(const __nv_bfloat16* __restrict__ A1h, const __nv_bfloat16* __restrict__ A1l,
          const __nv_bfloat16* __restrict__ W1h, const __nv_bfloat16* __restrict__ W1l,
          const float* __restrict__ bias, float* __restrict__ outf, int M, int N)
{
    constexpr int RB = K * 2, ATB = 128 * RB, BTB = 64 * RB, CH = K / 8;
    extern __shared__ __align__(16) char smem[];
    uint32_t sbase = smem_u32(smem);
    uint32_t sAhi = sbase, sAlo = sbase + ATB, sBhi = sbase + 2 * ATB, sBlo = sbase + 2 * ATB + BTB;

    int tid = threadIdx.x, lane = tid & 31, wid = tid >> 5;
    int wm  = (wid & 3) * 32;
    int wnw = (wid >> 2) * 32;
    int gm  = blockIdx.x * 128;
    int wn  = blockIdx.y * 64;

    float c[2][4][4];
    #pragma unroll
    for (int i = 0; i < 2; i++)
        #pragma unroll
        for (int j = 0; j < 4; j++)
            #pragma unroll
            for (int q = 0; q < 4; q++) c[i][j][q] = 0.f;

    int a_row = (lane & 15);
    int a_kof = (lane >> 1) & 8;
    int b_row = (lane & 7) + ((lane >> 1) & 8);
    int b_kof = lane & 8;

    #pragma unroll 2
    for (int cc = tid; cc < 128 * CH; cc += 256) {
        int row = cc / CH, ch = cc - row * CH;
        int grow = gm + row;
        int sz = (grow < M) ? 16 : 0;
        uint32_t doff = (uint32_t)(row * RB + ((ch ^ (row & 7)) << 4));
        size_t so = (size_t)grow * K + ch * 8;
        cpa16(sAhi + doff, A1h + so, sz);
        cpa16(sAlo + doff, A1l + so, sz);
    }
    #pragma unroll 2
    for (int cc = tid; cc < 64 * CH; cc += 256) {
        int n = cc / CH, ch = cc - n * CH;
        int gn = wn + n;
        int sz = (gn < N) ? 16 : 0;
        uint32_t doff = (uint32_t)(n * RB + ((ch ^ (n & 7)) << 4));
        size_t so = (size_t)gn * K + ch * 8;
        cpa16(sBhi + doff, W1h + so, sz);
        cpa16(sBlo + doff, W1l + so, sz);
    }
    cpa_wait();
    __syncthreads();
    mainloop128<RB>(sAhi, sAlo, sBhi, sBlo, c, wm, wnw, a_row, a_kof, b_row, b_kof, K);

    int g  = lane >> 2;
    int tc = (lane & 3) * 2;
    #pragma unroll
    for (int mt = 0; mt < 2; mt++) {
        #pragma unroll
        for (int nt = 0; nt < 4; nt++) {
            int col0 = wn + wnw + nt * 8 + tc;
            #pragma unroll
            for (int h = 0; h < 2; h++) {
                int row = gm + wm + mt * 16 + g + h * 8;
                if (row >= M) continue;
                float v0 = c[mt][nt][h * 2 + 0] + __ldg(&bias[col0 < N ? col0 : 0]);
                float v1 = c[mt][nt][h * 2 + 1] + __ldg(&bias[col0 + 1 < N ? col0 + 1 : 0]);
                size_t o = (size_t)row * N + col0;
                if (col0 + 1 < N) { outf[o] = v0; outf[o + 1] = v1; }
                else if (col0 < N) outf[o] = v0;
            }
        }
    }
}

// ---------------- fused heads GEMM ----------------
__global__ void __launch_bounds__(256)
heads_k(const __nv_bfloat16* __restrict__ Ah, const __nv_bfloat16* __restrict__ Al,
        float* __restrict__ o_fealab, float* __restrict__ o_logists,
        float* __restrict__ o_out, __nv_bfloat16* __restrict__ outh,
        __nv_bfloat16* __restrict__ outl, float* __restrict__ o_truelab,
        const float* __restrict__ gamma, const float* __restrict__ beta,
        const float* __restrict__ rmean, const float* __restrict__ rvar,
        const float* __restrict__ wtlin, const float* __restrict__ btl, int M)
{
    constexpr int K = 128, RB = 256, ATB = 128 * RB, BTB = 64 * RB, CH = 16;
    extern __shared__ __align__(16) char smem[];
    uint32_t sbase = smem_u32(smem);
    uint32_t sAhi = sbase, sAlo = sbase + ATB, sBhi = sbase + 2 * ATB, sBlo = sbase + 2 * ATB + BTB;

    int tid = threadIdx.x, lane = tid & 31, wid = tid >> 5;
    int wm  = (wid & 3) * 32;
    int wnw = (wid >> 2) * 32;
    int gm  = blockIdx.x * 128;
    int y   = blockIdx.y;
    int wn  = y * 64;
    int seg = (y < 5) ? 0 : (y < 7) ? 1 : 2;

    float c[2][4][4];
    #pragma unroll
    for (int i = 0; i < 2; i++)
        #pragma unroll
        for (int j = 0; j < 4; j++)
            #pragma unroll
            for (int q = 0; q < 4; q++) c[i][j][q] = 0.f;

    int a_row = (lane & 15);
    int a_kof = (lane >> 1) & 8;
    int b_row = (lane & 7) + ((lane >> 1) & 8);
    int b_kof = lane & 8;

    const __nv_bfloat16* Wh = g_wth + WT_HEADS;
    const __nv_bfloat16* Wl = g_wtl + WT_HEADS;

    #pragma unroll 2
    for (int cc = tid; cc < 128 * CH; cc += 256) {
        int row = cc / CH, ch = cc - row * CH;
        int grow = gm + row;
        int sz = (grow < M) ? 16 : 0;
        uint32_t doff = (uint32_t)(row * RB + ((ch ^ (row & 7)) << 4));
        size_t so = (size_t)grow * K + ch * 8;
        cpa16(sAhi + doff, Ah + so, sz);
        cpa16(sAlo + doff, Al + so, sz);
    }
    #pragma unroll 2
    for (int cc = tid; cc < 64 * CH; cc += 256) {
        int n = cc / CH, ch = cc - n * CH;
        int gn = wn + n;
        uint32_t doff = (uint32_t)(n * RB + ((ch ^ (n & 7)) << 4));
        size_t so = (size_t)gn * K + ch * 8;
        cpa16(sBhi + doff, Wh + so, 16);
        cpa16(sBlo + doff, Wl + so, 16);
    }
    cpa_wait();
    __syncthreads();
    mainloop128<RB>(sAhi, sAlo, sBhi, sBlo, c, wm, wnw, a_row, a_kof, b_row, b_kof, K);
    __syncthreads();

    int g  = lane >> 2;
    int tc = (lane & 3) * 2;
    float rsum[2][2] = {{0.f, 0.f}, {0.f, 0.f}};

    #pragma unroll
    for (int mt = 0; mt < 2; mt++) {
        #pragma unroll
        for (int nt = 0; nt < 4; nt++) {
            int gcol0 = wn + wnw + nt * 8 + tc;
            #pragma unroll
            for (int h = 0; h < 2; h++) {
                int row = gm + wm + mt * 16 + g + h * 8;
                if (row >= M) continue;
                float v0 = c[mt][nt][h * 2 + 0] + __ldg(&g_biascat[gcol0]);
                float v1 = c[mt][nt][h * 2 + 1] + __ldg(&g_biascat[gcol0 + 1]);
                if (seg == 2) {
                    int l0 = gcol0 - 448;
                    float s0 = __ldg(&gamma[l0]) * rsqrtf(__ldg(&rvar[l0]) + 1e-5f);
                    float s1 = __ldg(&gamma[l0 + 1]) * rsqrtf(__ldg(&rvar[l0 + 1]) + 1e-5f);
                    float p0 = v0 * s0 + (__ldg(&beta[l0]) - __ldg(&rmean[l0]) * s0);
                    float p1 = v1 * s1 + (__ldg(&beta[l0 + 1]) - __ldg(&rmean[l0 + 1]) * s1);
                    float t0 = tanhf(p0), t1 = tanhf(p1);
                    size_t o = (size_t)row * NBITS + l0;
                    o_out[o] = t0; o_out[o + 1] = t1;
                    *(uint32_t*)(outh + o) = pack_hi(t0, t1);
                    *(uint32_t*)(outl + o) = pack_lo(t0, t1);
                    rsum[mt][h] += p0 * __ldg(&wtlin[l0]) + p1 * __ldg(&wtlin[l0 + 1]);
                } else if (seg == 0) {
                    int l0 = gcol0;
                    if (l0 < 300)     o_fealab[(size_t)row * 300 + l0] = v0;
                    if (l0 + 1 < 300) o_fealab[(size_t)row * 300 + l0 + 1] = v1;
                } else {
                    int l0 = gcol0 - 320;
                    if (l0 < 100)     o_logists[(size_t)row * 100 + l0] = v0;
                    if (l0 + 1 < 100) o_logists[(size_t)row * 100 + l0 + 1] = v1;
                }
            }
        }
    }

    if (seg == 2) {
        float* tl = (float*)smem;   // reuse staging smem
        #pragma unroll
        for (int mt = 0; mt < 2; mt++)
            #pragma unroll
            for (int h = 0; h < 2; h++) {
                float s = rsum[mt][h];
                s += __shfl_xor_sync(0xffffffffu, s, 1);
                s += __shfl_xor_sync(0xffffffffu, s, 2);
                rsum[mt][h] = s;
            }
        __syncthreads();
        if ((lane & 3) == 0) {
            #pragma unroll
            for (int mt = 0; mt < 2; mt++)
                #pragma unroll
                for (int h = 0; h < 2; h++) {
                    int r = wm + mt * 16 + g + h * 8;
                    tl[r * 2 + (wnw >> 5)] = rsum[mt][h];
                }
        }
        __syncthreads();
        if (tid < 128) {
            int row = gm + tid;
            if (row < M) o_truelab[row] = tl[tid * 2] + tl[tid * 2 + 1] + __ldg(&btl[0]);
        }
    }
}

// ---------------- launch ----------------
extern "C" void kernel_launch(void* const* d_in, const int* in_sizes, int n_in,
                              void* d_out, int out_size)
{
    const float* features = (const float*)d_in[0];
    const int*   edges    = (const int*)d_in[1];
    const float* w1l = (const float*)d_in[2];
    const float* b1l = (const float*)d_in[3];
    const float* w1r = (const float*)d_in[4];
    const float* w2l = (const float*)d_in[5];
    const float* b2l = (const float*)d_in[6];
    const float* w2r = (const float*)d_in[7];
    const float* whd = (const float*)d_in[8];
    const float* bhd = (const float*)d_in[9];
    const float* wclas = (const float*)d_in[10];
    const float* bclas = (const float*)d_in[11];
    const float* wconv = (const float*)d_in[12];
    const float* bconv = (const float*)d_in[13];
    const float* gamma = (const float*)d_in[14];
    const float* beta  = (const float*)d_in[15];
    const float* rm    = (const float*)d_in[16];
    const float* rv    = (const float*)d_in[17];
    const float* wtl   = (const float*)d_in[18];
    const float* btl   = (const float*)d_in[19];
    const float* wcv   = (const float*)d_in[20];
    const float* bcv   = (const float*)d_in[21];

    float* out = (float*)d_out;
    float* o_logists = out;
    float* o_out     = out + (size_t)NN * NCLS;
    float* o_fealab  = o_out + (size_t)NN * NBITS;
    float* o_feacv   = o_fealab + (size_t)NN * HDIM;
    float* o_truelab = o_feacv + (size_t)NN * NCLS;

    const int* esrc = edges;
    const int* edst = edges + NE;

    float* p_h1f;
    __nv_bfloat16 *p_mh, *p_ml, *p_h2h, *p_h2l, *p_oh, *p_ol, *p_wth, *p_wtl;
    cudaGetSymbolAddress((void**)&p_h1f, g_h1f);
    cudaGetSymbolAddress((void**)&p_mh, g_mh);
    cudaGetSymbolAddress((void**)&p_ml, g_ml);
    cudaGetSymbolAddress((void**)&p_h2h, g_h2h);
    cudaGetSymbolAddress((void**)&p_h2l, g_h2l);
    cudaGetSymbolAddress((void**)&p_oh, g_oh);
    cudaGetSymbolAddress((void**)&p_ol, g_ol);
    cudaGetSymbolAddress((void**)&p_wth, g_wth);
    cudaGetSymbolAddress((void**)&p_wtl, g_wtl);

    const int SM128 = (2 * 128 + 2 * 64) * 128 * 2;  // 98304
    const int SM64  = (2 * 128 + 2 * 64) * 64 * 2;   // 49152
    cudaFuncSetAttribute(mm_layer<true, false>, cudaFuncAttributeMaxDynamicSharedMemorySize, SM128);
    cudaFuncSetAttribute(mm_layer<false, true>, cudaFuncAttributeMaxDynamicSharedMemorySize, SM128);
    cudaFuncSetAttribute(mm_kernel<64>, cudaFuncAttributeMaxDynamicSharedMemorySize, SM64);
    cudaFuncSetAttribute(heads_k, cudaFuncAttributeMaxDynamicSharedMemorySize, SM128);

    // 0: prep (weights, cursor zero, bias concat)
    prep_k<<<PB_TOTAL, 256>>>(w1l, w1r, w2l, w2r, whd, wclas, wconv, wcv,
                              bhd, bclas, bconv);
    // 1-3: CSR
    hist_k<<<512, 256>>>(edst);
    scan_all_k<<<1, 1024>>>();
    scatter_k<<<512, 256>>>(esrc, edst);

    const int AGG_BLOCKS = (NN * 32 + 255) / 256;
    const int GM = (NN + 127) / 128;  // 391

    // 4-5: layer 1 (features inline-converted)
    agg_k<<<AGG_BLOCKS, 256>>>(features, p_mh, p_ml);
    mm_layer<true, false><<<dim3(GM, 2), 256, SM128>>>(
        features, p_mh, p_ml,
        p_wth + WT_W1R, p_wtl + WT_W1R, p_wth + WT_W1L, p_wtl + WT_W1L,
        b1l, p_h1f, nullptr, nullptr, NN);
    // 6-7: layer 2 (h1f inline-converted; output = h2 planes only)
    agg_k<<<AGG_BLOCKS, 256>>>(p_h1f, p_mh, p_ml);
    mm_layer<false, true><<<dim3(GM, 2), 256, SM128>>>(
        p_h1f, p_mh, p_ml,
        p_wth + WT_W2R, p_wtl + WT_W2R, p_wth + WT_W2L, p_wtl + WT_W2L,
        b2l, nullptr, p_h2h, p_h2l, NN);

    // 8: fused heads
    heads_k<<<dim3(GM, 8), 256, SM128>>>(
        p_h2h, p_h2l, o_fealab, o_logists, o_out, p_oh, p_ol, o_truelab,
        gamma, beta, rm, rv, wtl, btl, NN);

    // 9: fea_convert
    mm_kernel<64><<<dim3(GM, 2), 256, SM64>>>(
        p_oh, p_ol, p_wth + WT_WCV, p_wtl + WT_WCV, bcv, o_feacv, NN, NCLS);
}